// round 4
// baseline (speedup 1.0000x reference)
#include <cuda_runtime.h>

// Analytic collapse of the 4-qubit, 2-layer circuit:
//   out[i] = sigmoid( (cos(x0)*cos(x1)*cos(x3) + 1) * 0.5 )
// RZ phases (weights) cancel in |amp|^2; the two CNOT-ring layers compose to
// a GF(2)-linear bit map whose q0 output is b0^b1^b3 of the initial basis
// index, giving <Z0> = cos(x0)cos(x1)cos(x3) for the RY product state.
//
// B = 524288 is even, so the 2-rows-per-thread path has no tail in practice;
// a scalar tail guard is kept for generality.

__global__ __launch_bounds__(256)
void dqc_kernel(const float4* __restrict__ in, float* __restrict__ out, int n) {
    int i = blockIdx.x * blockDim.x + threadIdx.x;       // pair index
    int npair = n >> 1;
    int stride = gridDim.x * blockDim.x;
    for (; i < npair; i += stride) {
        float4 a = in[2 * i];
        float4 b = in[2 * i + 1];
        float za = cosf(a.x) * cosf(a.y) * cosf(a.w);
        float zb = cosf(b.x) * cosf(b.y) * cosf(b.w);
        float2 r;
        r.x = 1.0f / (1.0f + __expf(-(za + 1.0f) * 0.5f));
        r.y = 1.0f / (1.0f + __expf(-(zb + 1.0f) * 0.5f));
        reinterpret_cast<float2*>(out)[i] = r;
    }
    // tail (only if n is odd)
    if ((n & 1) && blockIdx.x == 0 && threadIdx.x == 0) {
        float4 a = in[n - 1];
        float z = cosf(a.x) * cosf(a.y) * cosf(a.w);
        out[n - 1] = 1.0f / (1.0f + __expf(-(z + 1.0f) * 0.5f));
    }
}

extern "C" void kernel_launch(void* const* d_in, const int* in_sizes, int n_in,
                              void* d_out, int out_size) {
    const float4* inputs = (const float4*)d_in[0];   // [B,4] float32, 16B rows
    float* out = (float*)d_out;                      // [B] float32
    int B = in_sizes[0] / 4;
    int threads = 256;
    int blocks = ((B / 2) + threads - 1) / threads;  // B=2^19 -> 1024 blocks
    if (blocks < 1) blocks = 1;
    if (blocks > 8192) blocks = 8192;
    dqc_kernel<<<blocks, threads>>>(inputs, out, B);
}